// round 4
// baseline (speedup 1.0000x reference)
#include <cuda_runtime.h>

// MS-SSIM loss, 4 scales. Fused separable-Gaussian SSIM + 2x2 avg-pool.
// v4: A/B interleaved as float2 end-to-end so f32x2 (FFMA2/FMUL2) operands
//     are native 64-bit pairs (no pack MOV churn, the v3 failure mode).
//     Pooled scratch is float2; paired hbuf with STS.128/LDS.64.

#define NPLANES 48
typedef unsigned long long ull;

// ---- scratch (static device globals; no allocations allowed) ----
__device__ float g_acc[4];
__device__ float2 g_p1[48 * 256 * 256];
__device__ float2 g_p2[48 * 128 * 128];
__device__ float2 g_p3[48 * 64 * 64];

__global__ void init_acc_kernel() {
    if (threadIdx.x < 4) g_acc[threadIdx.x] = 0.0f;
}

// ---- packed f32x2 helpers ----
__device__ __forceinline__ ull pack2(float lo, float hi) {
    ull r;
    asm("mov.b64 %0, {%1, %2};" : "=l"(r) : "f"(lo), "f"(hi));
    return r;
}
__device__ __forceinline__ void unpack2(ull v, float& lo, float& hi) {
    asm("mov.b64 {%0, %1}, %2;" : "=f"(lo), "=f"(hi) : "l"(v));
}
__device__ __forceinline__ void ffma2(ull& acc, ull a, ull b) {
    asm("fma.rn.f32x2 %0, %1, %2, %0;" : "+l"(acc) : "l"(a), "l"(b));
}
__device__ __forceinline__ ull fmul2(ull a, ull b) {
    ull d;
    asm("mul.rn.f32x2 %0, %1, %2;" : "=l"(d) : "l"(a), "l"(b));
    return d;
}

// Gaussian(11, sigma=1.5), normalized.
#define G_LIST { \
    0.00102838f, 0.00759875f, 0.03600077f, 0.10936070f, 0.21300553f, \
    0.26601172f, \
    0.21300553f, 0.10936070f, 0.03600077f, 0.00759875f, 0.00102838f }

// TW: tile width, TH: tile height, RPT: rows/thread in V-pass.
template<int TW, int TH, int RPT>
__global__ void __launch_bounds__(TW * TH / RPT)
ssim_kernel(const float* __restrict__ A0, const float* __restrict__ B0,
            int scale, int W, int do_pool)
{
    constexpr int NT    = TW * TH / RPT;   // threads per block
    constexpr int IH    = TH + 10;         // rows incl. halo
    constexpr int LW4   = TW / 4 + 4;      // float4-of-floats per row (scale 0 path)
    constexpr int LP    = 4 * LW4;         // window width in pixels (= float2 cols)
    constexpr int SLOTS = TW / 4;          // 4-wide output groups per row
    constexpr int HP    = TW + 2;          // hbuf pitch (even -> 16B rows)
    constexpr int HPX   = TW + 4;          // hx pitch (mult of 4 -> 16B rows)

    __shared__ __align__(16) float2 sAB[IH][LP];
    __shared__ __align__(16) ull h12[IH][HP];    // (mu1, mu2) packed
    __shared__ __align__(16) ull h1122[IH][HP];  // (E[x^2], E[y^2]) packed
    __shared__ __align__(16) float hx[IH][HPX];  // E[x*y]
    __shared__ float red[NT / 32];

    const float G[11] = G_LIST;

    const int H = W;
    const float2* P;
    switch (scale) {
        case 1:  P = g_p1; break;
        case 2:  P = g_p2; break;
        default: P = g_p3; break;
    }

    const int tx    = blockIdx.x * TW;
    const int ty    = blockIdx.y * TH;
    const int plane = blockIdx.z;
    const size_t pbase = (size_t)plane * (size_t)W * (size_t)H;
    const int tid = threadIdx.x;

    // ---- stage 1: load tile + halo, interleaved (a,b) pairs in smem ----
    if (scale == 0) {
        for (int i = tid; i < IH * LW4; i += NT) {
            int r = i / LW4;
            int s = i - r * LW4;
            int gy = ty + r - 5;
            int gx = tx + 4 * s - 8;
            float4 a = make_float4(0.f, 0.f, 0.f, 0.f);
            float4 b = a;
            if ((unsigned)gy < (unsigned)H && (unsigned)gx <= (unsigned)(W - 4)) {
                size_t idx = pbase + (size_t)gy * W + gx;
                a = *reinterpret_cast<const float4*>(A0 + idx);
                b = *reinterpret_cast<const float4*>(B0 + idx);
            }
            float4 lo = make_float4(a.x, b.x, a.y, b.y);
            float4 hi = make_float4(a.z, b.z, a.w, b.w);
            *reinterpret_cast<float4*>(&sAB[r][4 * s])     = lo;
            *reinterpret_cast<float4*>(&sAB[r][4 * s + 2]) = hi;
        }
    } else {
        constexpr int NF4 = LP / 2;   // float4 loads per row (2 px each)
        for (int i = tid; i < IH * NF4; i += NT) {
            int r = i / NF4;
            int s = i - r * NF4;
            int gy = ty + r - 5;
            int gx = tx + 2 * s - 8;   // pixel index (even -> 16B aligned)
            float4 v = make_float4(0.f, 0.f, 0.f, 0.f);
            if ((unsigned)gy < (unsigned)H && (unsigned)gx <= (unsigned)(W - 2)) {
                v = *reinterpret_cast<const float4*>(P + pbase + (size_t)gy * W + gx);
            }
            *reinterpret_cast<float4*>(&sAB[r][2 * s]) = v;
        }
    }
    __syncthreads();

    // ---- fused 2x2 avg-pool for the next scale ----
    if (do_pool) {
        constexpr int PW = TW / 2, PH = TH / 2;
        if (tid < PW * PH) {
            int pr = tid / PW;
            int pc = tid - pr * PW;
            int r = 5 + 2 * pr;
            int c = 8 + 2 * pc;
            float2 q00 = sAB[r][c],     q01 = sAB[r][c + 1];
            float2 q10 = sAB[r + 1][c], q11 = sAB[r + 1][c + 1];
            float2 o;
            o.x = 0.25f * (q00.x + q01.x + q10.x + q11.x);
            o.y = 0.25f * (q00.y + q01.y + q10.y + q11.y);
            int pW = W >> 1;
            size_t pidx = (size_t)plane * pW * pW
                        + (size_t)((ty >> 1) + pr) * pW + ((tx >> 1) + pc);
            float2* PD;
            switch (scale) {
                case 0:  PD = g_p1; break;
                case 1:  PD = g_p2; break;
                default: PD = g_p3; break;
            }
            PD[pidx] = o;
        }
    }

    // ---- stage 2: horizontal 11-tap pass, 4 outputs/thread, f32x2 math ----
    {
        ull g2[11];
        #pragma unroll
        for (int k = 0; k < 11; k++) g2[k] = pack2(G[k], G[k]);

        for (int i = tid; i < IH * SLOTS; i += NT) {
            int r  = i / SLOTS;
            int sl = i - r * SLOTS;
            int c0 = 4 * sl;
            ull wab[20];
            #pragma unroll
            for (int q = 0; q < 10; q++) {
                ulonglong2 u = *reinterpret_cast<const ulonglong2*>(&sAB[r][c0 + 2 * q]);
                wab[2 * q]     = u.x;
                wab[2 * q + 1] = u.y;
            }
            ull m12p[4], m1122p[4];
            float mx[4];
            #pragma unroll
            for (int j = 0; j < 4; j++) { m12p[j] = 0ull; m1122p[j] = 0ull; mx[j] = 0.f; }
            #pragma unroll
            for (int t = 0; t < 14; t++) {
                ull vab = wab[t + 3];
                float va, vb;
                unpack2(vab, va, vb);
                ull aabb = fmul2(vab, vab);
                float ab = va * vb;
                #pragma unroll
                for (int j = 0; j < 4; j++) {
                    int k = t - j;
                    if (k >= 0 && k < 11) {
                        ffma2(m12p[j],   vab,  g2[k]);
                        ffma2(m1122p[j], aabb, g2[k]);
                        mx[j] = fmaf(ab, G[k], mx[j]);
                    }
                }
            }
            *reinterpret_cast<ulonglong2*>(&h12[r][c0])       = make_ulonglong2(m12p[0],   m12p[1]);
            *reinterpret_cast<ulonglong2*>(&h12[r][c0 + 2])   = make_ulonglong2(m12p[2],   m12p[3]);
            *reinterpret_cast<ulonglong2*>(&h1122[r][c0])     = make_ulonglong2(m1122p[0], m1122p[1]);
            *reinterpret_cast<ulonglong2*>(&h1122[r][c0 + 2]) = make_ulonglong2(m1122p[2], m1122p[3]);
            *reinterpret_cast<float4*>(&hx[r][c0]) = make_float4(mx[0], mx[1], mx[2], mx[3]);
        }
    }
    __syncthreads();

    // ---- stage 3: vertical 11-tap pass (f32x2), SSIM map, reduce ----
    float acc = 0.0f;
    {
        ull g2[11];
        #pragma unroll
        for (int k = 0; k < 11; k++) g2[k] = pack2(G[k], G[k]);

        const int c  = tid % TW;
        const int r0 = (tid / TW) * RPT;
        ull s12p[RPT], s1122p[RPT];
        float sx[RPT];
        #pragma unroll
        for (int j = 0; j < RPT; j++) { s12p[j] = 0ull; s1122p[j] = 0ull; sx[j] = 0.f; }

        #pragma unroll
        for (int t = 0; t < RPT + 10; t++) {
            ull v12   = h12[r0 + t][c];
            ull v1122 = h1122[r0 + t][c];
            float vx  = hx[r0 + t][c];
            #pragma unroll
            for (int j = 0; j < RPT; j++) {
                int k = t - j;
                if (k >= 0 && k < 11) {
                    ffma2(s12p[j],   v12,   g2[k]);
                    ffma2(s1122p[j], v1122, g2[k]);
                    sx[j] = fmaf(vx, G[k], sx[j]);
                }
            }
        }
        const float C1 = 1e-4f;
        const float C2 = 9e-4f;
        #pragma unroll
        for (int j = 0; j < RPT; j++) {
            float mu1, mu2, e11, e22;
            unpack2(s12p[j], mu1, mu2);
            unpack2(s1122p[j], e11, e22);
            float mu1s = mu1 * mu1;
            float mu2s = mu2 * mu2;
            float mu12 = mu1 * mu2;
            float sg1  = e11 - mu1s;
            float sg2  = e22 - mu2s;
            float sg12 = sx[j] - mu12;
            float num = (2.0f * mu12 + C1) * (2.0f * sg12 + C2);
            float den = (mu1s + mu2s + C1) * (sg1 + sg2 + C2);
            acc += __fdividef(num, den);
        }
    }

    // ---- block reduction -> one atomic per block ----
    #pragma unroll
    for (int o = 16; o > 0; o >>= 1)
        acc += __shfl_down_sync(0xffffffffu, acc, o);
    if ((tid & 31) == 0) red[tid >> 5] = acc;
    __syncthreads();
    if (tid == 0) {
        float s = 0.f;
        #pragma unroll
        for (int w = 0; w < NT / 32; w++) s += red[w];
        atomicAdd(&g_acc[scale], s);
    }
}

__global__ void finalize_kernel(float* __restrict__ out) {
    const float w[4] = {0.0448f, 0.2856f, 0.3001f, 0.2363f};
    float loss = 0.0f;
    float cnt = 48.0f * 512.0f * 512.0f;
    #pragma unroll
    for (int s = 0; s < 4; s++) {
        loss += w[s] * (1.0f - g_acc[s] / cnt);
        cnt *= 0.25f;
    }
    out[0] = loss;
}

extern "C" void kernel_launch(void* const* d_in, const int* in_sizes, int n_in,
                              void* d_out, int out_size) {
    const float* img1 = (const float*)d_in[0];
    const float* img2 = (const float*)d_in[1];
    float* out = (float*)d_out;

    init_acc_kernel<<<1, 32>>>();

    // scale 0: 512x512, 32x32 tiles, 256 thr
    ssim_kernel<32, 32, 4><<<dim3(16, 16, NPLANES), 256>>>(img1, img2, 0, 512, 1);
    // scale 1: 256x256, 32x32 tiles
    ssim_kernel<32, 32, 4><<<dim3(8, 8, NPLANES), 256>>>(nullptr, nullptr, 1, 256, 1);
    // scale 2: 128x128, 16x16 tiles (3072 blocks: shorter critical path)
    ssim_kernel<16, 16, 2><<<dim3(8, 8, NPLANES), 128>>>(nullptr, nullptr, 2, 128, 1);
    // scale 3: 64x64, 16x8 tiles (1536 blocks)
    ssim_kernel<16, 8, 1><<<dim3(4, 8, NPLANES), 128>>>(nullptr, nullptr, 3, 64, 0);

    finalize_kernel<<<1, 1>>>(out);
}

// round 5
// speedup vs baseline: 1.0896x; 1.0896x over previous
#include <cuda_runtime.h>

// MS-SSIM loss, 4 scales. Fused separable-Gaussian SSIM + 2x2 avg-pool.
// v5: sum/diff reformulation. s=a+b, d=a-b; convolve only packed (s,d) and
//     (s^2,d^2) (2 f32x2 channels; SSIM needs only mu1mu2, mu1^2+mu2^2,
//     sig1+sig2, sig12 which are all recoverable). Pool propagates (s,d).

#define NPLANES 48
typedef unsigned long long ull;

// ---- scratch (static device globals; no allocations allowed) ----
__device__ float g_acc[4];
__device__ float2 g_p1[48 * 256 * 256];
__device__ float2 g_p2[48 * 128 * 128];
__device__ float2 g_p3[48 * 64 * 64];

__global__ void init_acc_kernel() {
    if (threadIdx.x < 4) g_acc[threadIdx.x] = 0.0f;
}

// ---- packed f32x2 helpers ----
__device__ __forceinline__ ull pack2(float lo, float hi) {
    ull r;
    asm("mov.b64 %0, {%1, %2};" : "=l"(r) : "f"(lo), "f"(hi));
    return r;
}
__device__ __forceinline__ void unpack2(ull v, float& lo, float& hi) {
    asm("mov.b64 {%0, %1}, %2;" : "=f"(lo), "=f"(hi) : "l"(v));
}
__device__ __forceinline__ void ffma2(ull& acc, ull a, ull b) {
    asm("fma.rn.f32x2 %0, %1, %2, %0;" : "+l"(acc) : "l"(a), "l"(b));
}
__device__ __forceinline__ ull fmul2(ull a, ull b) {
    ull d;
    asm("mul.rn.f32x2 %0, %1, %2;" : "=l"(d) : "l"(a), "l"(b));
    return d;
}

// Gaussian(11, sigma=1.5), normalized.
#define G_LIST { \
    0.00102838f, 0.00759875f, 0.03600077f, 0.10936070f, 0.21300553f, \
    0.26601172f, \
    0.21300553f, 0.10936070f, 0.03600077f, 0.00759875f, 0.00102838f }

// TW: tile width, TH: tile height, RPT: rows/thread in V-pass.
template<int TW, int TH, int RPT>
__global__ void __launch_bounds__(TW * TH / RPT)
ssim_kernel(const float* __restrict__ A0, const float* __restrict__ B0,
            int scale, int W, int do_pool)
{
    constexpr int NT    = TW * TH / RPT;   // threads per block
    constexpr int IH    = TH + 10;         // rows incl. halo
    constexpr int LW4   = TW / 4 + 4;      // float4 slots per row (scale-0 path)
    constexpr int LP    = 4 * LW4;         // row width in (s,d) pixels
    constexpr int SLOTS = TW / 4;          // 4-wide output groups per row
    constexpr int HP    = TW + 2;          // hbuf pitch (even -> 16B rows)

    __shared__ __align__(16) float2 sSD[IH][LP];  // (s, d) per pixel
    __shared__ __align__(16) ull h1[IH][HP];      // conv (s, d)      packed
    __shared__ __align__(16) ull h2[IH][HP];      // conv (s^2, d^2)  packed
    __shared__ float red[NT / 32];

    const float G[11] = G_LIST;

    const int H = W;
    const float2* P;
    switch (scale) {
        case 1:  P = g_p1; break;
        case 2:  P = g_p2; break;
        default: P = g_p3; break;
    }

    const int tx    = blockIdx.x * TW;
    const int ty    = blockIdx.y * TH;
    const int plane = blockIdx.z;
    const size_t pbase = (size_t)plane * (size_t)W * (size_t)H;
    const int tid = threadIdx.x;

    // ---- stage 1: load tile + halo, transform to interleaved (s,d) ----
    if (scale == 0) {
        for (int i = tid; i < IH * LW4; i += NT) {
            int r = i / LW4;
            int s = i - r * LW4;
            int gy = ty + r - 5;
            int gx = tx + 4 * s - 8;
            float4 a = make_float4(0.f, 0.f, 0.f, 0.f);
            float4 b = a;
            if ((unsigned)gy < (unsigned)H && (unsigned)gx <= (unsigned)(W - 4)) {
                size_t idx = pbase + (size_t)gy * W + gx;
                a = *reinterpret_cast<const float4*>(A0 + idx);
                b = *reinterpret_cast<const float4*>(B0 + idx);
            }
            float4 lo = make_float4(a.x + b.x, a.x - b.x, a.y + b.y, a.y - b.y);
            float4 hi = make_float4(a.z + b.z, a.z - b.z, a.w + b.w, a.w - b.w);
            *reinterpret_cast<float4*>(&sSD[r][4 * s])     = lo;
            *reinterpret_cast<float4*>(&sSD[r][4 * s + 2]) = hi;
        }
    } else {
        constexpr int NF4 = LP / 2;   // float4 loads per row (2 (s,d) px each)
        for (int i = tid; i < IH * NF4; i += NT) {
            int r = i / NF4;
            int s = i - r * NF4;
            int gy = ty + r - 5;
            int gx = tx + 2 * s - 8;
            float4 v = make_float4(0.f, 0.f, 0.f, 0.f);
            if ((unsigned)gy < (unsigned)H && (unsigned)gx <= (unsigned)(W - 2)) {
                v = *reinterpret_cast<const float4*>(P + pbase + (size_t)gy * W + gx);
            }
            *reinterpret_cast<float4*>(&sSD[r][2 * s]) = v;
        }
    }
    __syncthreads();

    // ---- fused 2x2 avg-pool for the next scale ((s,d) is linear) ----
    if (do_pool) {
        constexpr int PW = TW / 2, PH = TH / 2;
        if (tid < PW * PH) {
            int pr = tid / PW;
            int pc = tid - pr * PW;
            int r = 5 + 2 * pr;
            int c = 8 + 2 * pc;
            float2 q00 = sSD[r][c],     q01 = sSD[r][c + 1];
            float2 q10 = sSD[r + 1][c], q11 = sSD[r + 1][c + 1];
            float2 o;
            o.x = 0.25f * (q00.x + q01.x + q10.x + q11.x);
            o.y = 0.25f * (q00.y + q01.y + q10.y + q11.y);
            int pW = W >> 1;
            size_t pidx = (size_t)plane * pW * pW
                        + (size_t)((ty >> 1) + pr) * pW + ((tx >> 1) + pc);
            float2* PD;
            switch (scale) {
                case 0:  PD = g_p1; break;
                case 1:  PD = g_p2; break;
                default: PD = g_p3; break;
            }
            PD[pidx] = o;
        }
    }

    // ---- stage 2: horizontal 11-tap pass, 4 outputs/thread, f32x2 math ----
    {
        ull g2[11];
        #pragma unroll
        for (int k = 0; k < 11; k++) g2[k] = pack2(G[k], G[k]);

        for (int i = tid; i < IH * SLOTS; i += NT) {
            int r  = i / SLOTS;
            int sl = i - r * SLOTS;
            int c0 = 4 * sl;
            ull w[20];
            #pragma unroll
            for (int q = 0; q < 10; q++) {
                ulonglong2 u = *reinterpret_cast<const ulonglong2*>(&sSD[r][c0 + 2 * q]);
                w[2 * q]     = u.x;
                w[2 * q + 1] = u.y;
            }
            ull a1[4], a2[4];
            #pragma unroll
            for (int j = 0; j < 4; j++) { a1[j] = 0ull; a2[j] = 0ull; }
            #pragma unroll
            for (int t = 0; t < 14; t++) {
                ull v  = w[t + 3];
                ull v2 = fmul2(v, v);
                #pragma unroll
                for (int j = 0; j < 4; j++) {
                    int k = t - j;
                    if (k >= 0 && k < 11) {
                        ffma2(a1[j], v,  g2[k]);
                        ffma2(a2[j], v2, g2[k]);
                    }
                }
            }
            *reinterpret_cast<ulonglong2*>(&h1[r][c0])     = make_ulonglong2(a1[0], a1[1]);
            *reinterpret_cast<ulonglong2*>(&h1[r][c0 + 2]) = make_ulonglong2(a1[2], a1[3]);
            *reinterpret_cast<ulonglong2*>(&h2[r][c0])     = make_ulonglong2(a2[0], a2[1]);
            *reinterpret_cast<ulonglong2*>(&h2[r][c0 + 2]) = make_ulonglong2(a2[2], a2[3]);
        }
    }
    __syncthreads();

    // ---- stage 3: vertical 11-tap pass (f32x2), SSIM map, reduce ----
    float acc = 0.0f;
    {
        ull g2[11];
        #pragma unroll
        for (int k = 0; k < 11; k++) g2[k] = pack2(G[k], G[k]);

        const int c  = tid % TW;
        const int r0 = (tid / TW) * RPT;
        ull s1[RPT], s2[RPT];
        #pragma unroll
        for (int j = 0; j < RPT; j++) { s1[j] = 0ull; s2[j] = 0ull; }

        #pragma unroll
        for (int t = 0; t < RPT + 10; t++) {
            ull v1 = h1[r0 + t][c];
            ull v2 = h2[r0 + t][c];
            #pragma unroll
            for (int j = 0; j < RPT; j++) {
                int k = t - j;
                if (k >= 0 && k < 11) {
                    ffma2(s1[j], v1, g2[k]);
                    ffma2(s2[j], v2, g2[k]);
                }
            }
        }
        const float C1 = 1e-4f;
        const float C2 = 9e-4f;
        #pragma unroll
        for (int j = 0; j < RPT; j++) {
            float mus, mud, es2, ed2;
            unpack2(s1[j], mus, mud);
            unpack2(s2[j], es2, ed2);
            float A = mus * mus;                    // mu_s^2
            float B = mud * mud;                    // mu_d^2
            float mu12  = 0.25f * (A - B);          // mu1*mu2
            float musq  = 0.5f  * (A + B);          // mu1^2 + mu2^2
            float sigs  = 0.5f  * (es2 + ed2) - musq;   // sig1^2 + sig2^2
            float sig12 = 0.25f * (es2 - ed2) - mu12;   // sig12
            float num = (2.0f * mu12 + C1) * (2.0f * sig12 + C2);
            float den = (musq + C1) * (sigs + C2);
            acc += __fdividef(num, den);
        }
    }

    // ---- block reduction -> one atomic per block ----
    #pragma unroll
    for (int o = 16; o > 0; o >>= 1)
        acc += __shfl_down_sync(0xffffffffu, acc, o);
    if ((tid & 31) == 0) red[tid >> 5] = acc;
    __syncthreads();
    if (tid == 0) {
        float s = 0.f;
        #pragma unroll
        for (int w = 0; w < NT / 32; w++) s += red[w];
        atomicAdd(&g_acc[scale], s);
    }
}

__global__ void finalize_kernel(float* __restrict__ out) {
    const float w[4] = {0.0448f, 0.2856f, 0.3001f, 0.2363f};
    float loss = 0.0f;
    float cnt = 48.0f * 512.0f * 512.0f;
    #pragma unroll
    for (int s = 0; s < 4; s++) {
        loss += w[s] * (1.0f - g_acc[s] / cnt);
        cnt *= 0.25f;
    }
    out[0] = loss;
}

extern "C" void kernel_launch(void* const* d_in, const int* in_sizes, int n_in,
                              void* d_out, int out_size) {
    const float* img1 = (const float*)d_in[0];
    const float* img2 = (const float*)d_in[1];
    float* out = (float*)d_out;

    init_acc_kernel<<<1, 32>>>();

    // scale 0: 512x512, 32x32 tiles, 256 thr
    ssim_kernel<32, 32, 4><<<dim3(16, 16, NPLANES), 256>>>(img1, img2, 0, 512, 1);
    // scale 1: 256x256, 32x32 tiles
    ssim_kernel<32, 32, 4><<<dim3(8, 8, NPLANES), 256>>>(nullptr, nullptr, 1, 256, 1);
    // scale 2: 128x128, 32x16 tiles (R3's best config for this scale)
    ssim_kernel<32, 16, 2><<<dim3(4, 8, NPLANES), 256>>>(nullptr, nullptr, 2, 128, 1);
    // scale 3: 64x64, 16x16 tiles
    ssim_kernel<16, 16, 2><<<dim3(4, 4, NPLANES), 128>>>(nullptr, nullptr, 3, 64, 0);

    finalize_kernel<<<1, 1>>>(out);
}